// round 11
// baseline (speedup 1.0000x reference)
#include <cuda_runtime.h>

// Fused shift + grouped conv(H taps, w1) + grouped conv(W taps, w2).
//
// x:  (1,512,14,14) fp32, channel c = i*8 + o   (i=0..63, o=0..7)
// Stage 1: y[k,o,h,w] = sum_{i,j} x[(h+j-2) mod 14][..] * w1[k,i,j],
//          tap j contributes iff 0 <= h+j-1 < 14 (roll +1 along H, zero-pad).
//          Loads always issued (mod-14 row in-bounds); dead edge taps are
//          zeroed AT STAGING TIME (h==0 tap j=0, h==13 tap j=2) so the hot
//          loop has no predicates at all.
// Stage 2: out[(i2*16+k)*196 + h*14 + w] = sum_{o,t} y[k,o,h,w-1+t] * w2[i2,o,t]
//          ys is stored zero-padded along W so stage 2 has no edge predicates.
//
// Grid (8 k-pairs, 14 h) = 112 CTAs, 896 threads (28 warps).
// ws1 layout is TRANSPOSED to [kl][j][i64] so each stage-1 thread's weights
// for its 4 contiguous i's are 6 hoisted LDS.128; the loop is pure FMA.

__device__ __forceinline__ float2 ldg64v(const float2* p) {
    float2 v;
    asm volatile("ld.global.nc.v2.f32 {%0,%1},[%2];"
                 : "=f"(v.x), "=f"(v.y) : "l"(p));
    return v;
}

__global__ void __launch_bounds__(896, 1) fused_kernel(
    const float* __restrict__ x,
    const float* __restrict__ w1,
    const float* __restrict__ w2,
    float* __restrict__ out)
{
    __shared__ __align__(16) float ws1[384];    // [kl][j][i64], edge taps zeroed
    __shared__ float ws2[768];                  // all of w2
    __shared__ float part[16 * 2 * 8 * 16];     // [g][kl][o][w pad 16]
    __shared__ float ys[2 * 8 * 16];            // [kl][o][1+w..14, 0/15 = zero]

    const int kp  = blockIdx.x;   // 0..7   (k = kp*2 + kl)
    const int h   = blockIdx.y;   // 0..13
    const int tid = threadIdx.x;  // 0..895

    // ---- stage-1 thread decode ----
    const int g   = tid / 56;          // 0..15 (i-split)
    const int rem = tid - g * 56;
    const int o   = rem / 7;           // 0..7
    const int wp  = rem - o * 7;       // 0..6  -> w0 = 2*wp
    const int w0  = wp * 2;

    // taps: source rows (mod-14 roll); always in-bounds
    const int r0 = (h + 12) % 14;      // j=0 (weight zeroed iff h == 0)
    const int r1 = (h + 13) % 14;      // j=1, always
    const int r2 = h;                  // j=2 (weight zeroed iff h == 13)

    const float2* __restrict__ px = (const float2*)x;
    // float2 index of x[(i*8+o)*196 + r*14 + w0] = (i*8+o)*98 + r*7 + wp
    const int e0 = o * 98 + r0 * 7 + wp;
    const int e1 = o * 98 + r1 * 7 + wp;
    const int e2 = o * 98 + r2 * 7 + wp;
    const int ib = g * 4;

    // ---- front-batch all 12 x loads (volatile: cannot sink past barrier) ----
    float2 xv0[4], xv1[4], xv2[4];
    #pragma unroll
    for (int ii = 0; ii < 4; ii++) {
        const int off = (ib + ii) * 784;   // i*8*98
        xv0[ii] = ldg64v(px + off + e0);
        xv1[ii] = ldg64v(px + off + e1);
        xv2[ii] = ldg64v(px + off + e2);
    }

    // ---- weight staging: ws1[kl*192 + j*64 + i] = w1[kp*2+kl][i][j] ----
    if (tid < 384) {
        const int kl = tid / 192;
        const int r  = tid - kl * 192;
        const int j  = r / 64;
        const int i  = r - j * 64;
        float v = __ldg(w1 + (kp * 2 + kl) * 192 + i * 3 + j);
        if ((j == 0 && h == 0) || (j == 2 && h == 13)) v = 0.f;
        ws1[tid] = v;
    }
    if (tid < 768) ws2[tid] = __ldg(w2 + tid);

    __syncthreads();   // ws1/ws2 visible; x loads in flight behind it

    // ---- hoist this thread's 24 weights: 6 LDS.128 ----
    const float4 wa0 = *(const float4*)(ws1 +   0 + ib);   // kl=0, j=0
    const float4 wb0 = *(const float4*)(ws1 +  64 + ib);   // kl=0, j=1
    const float4 wc0 = *(const float4*)(ws1 + 128 + ib);   // kl=0, j=2
    const float4 wa1 = *(const float4*)(ws1 + 192 + ib);   // kl=1, j=0
    const float4 wb1 = *(const float4*)(ws1 + 256 + ib);   // kl=1, j=1
    const float4 wc1 = *(const float4*)(ws1 + 320 + ib);   // kl=1, j=2
    const float wA0[4] = {wa0.x, wa0.y, wa0.z, wa0.w};
    const float wB0[4] = {wb0.x, wb0.y, wb0.z, wb0.w};
    const float wC0[4] = {wc0.x, wc0.y, wc0.z, wc0.w};
    const float wA1[4] = {wa1.x, wa1.y, wa1.z, wa1.w};
    const float wB1[4] = {wb1.x, wb1.y, wb1.z, wb1.w};
    const float wC1[4] = {wc1.x, wc1.y, wc1.z, wc1.w};

    // ---- stage 1 FMAs: pure arithmetic, no loads, no predicates ----
    float a0A = 0.f, a0B = 0.f;        // kl=0: w0, w0+1
    float a1A = 0.f, a1B = 0.f;        // kl=1: w0, w0+1
    #pragma unroll
    for (int ii = 0; ii < 4; ii++) {
        a0A = fmaf(xv0[ii].x, wA0[ii], a0A);
        a0A = fmaf(xv1[ii].x, wB0[ii], a0A);
        a0A = fmaf(xv2[ii].x, wC0[ii], a0A);
        a0B = fmaf(xv0[ii].y, wA0[ii], a0B);
        a0B = fmaf(xv1[ii].y, wB0[ii], a0B);
        a0B = fmaf(xv2[ii].y, wC0[ii], a0B);
        a1A = fmaf(xv0[ii].x, wA1[ii], a1A);
        a1A = fmaf(xv1[ii].x, wB1[ii], a1A);
        a1A = fmaf(xv2[ii].x, wC1[ii], a1A);
        a1B = fmaf(xv0[ii].y, wA1[ii], a1B);
        a1B = fmaf(xv1[ii].y, wB1[ii], a1B);
        a1B = fmaf(xv2[ii].y, wC1[ii], a1B);
    }
    {
        float2* pp = (float2*)part;
        // part[g][kl][o][w16]: float2 index = (g*256 + kl*128 + o*16 + w0)/2
        pp[(g * 256 + o * 16 + w0) >> 1]       = make_float2(a0A, a0B);
        pp[(g * 256 + 128 + o * 16 + w0) >> 1] = make_float2(a1A, a1B);
    }
    __syncthreads();

    // ---- reduce the 16 i-partials per (kl,o,w): 224 threads; pad zeros ----
    if (tid < 224) {
        const int kl  = tid / 112;
        const int r2d = tid - kl * 112;
        const int oo  = r2d / 14;
        const int ww  = r2d - oo * 14;
        const int b   = kl * 128 + oo * 16 + ww;
        float s0 = 0.f, s1 = 0.f, s2 = 0.f, s3 = 0.f;
        #pragma unroll
        for (int gg = 0; gg < 4; gg++) {
            s0 += part[(gg)      * 256 + b];
            s1 += part[(gg + 4)  * 256 + b];
            s2 += part[(gg + 8)  * 256 + b];
            s3 += part[(gg + 12) * 256 + b];
        }
        // ys stores w at column ww+1; columns 0 and 15 are zero pads
        ys[kl * 128 + oo * 16 + ww + 1] = (s0 + s1) + (s2 + s3);
    } else if (tid < 256) {
        // zero the pad columns: 32 threads cover [kl][o] x {0, 15}
        const int z  = tid - 224;        // 0..31
        const int kl = z / 16;
        const int oz = (z % 16) / 2;
        const int cp = (z & 1) ? 15 : 0;
        ys[kl * 128 + oz * 16 + cp] = 0.f;
    }
    __syncthreads();

    // ---- stage 2: thread = (i2, kl, wp); no edge predicates (ys padded) ----
    if (tid < 448) {
        const int i2  = tid / 14;          // 0..31
        const int r2d = tid - i2 * 14;
        const int kl  = r2d / 7;           // 0..1
        const int wp2 = r2d - kl * 7;      // 0..6
        const int u0  = wp2 * 2;           // w = u0, u0+1
        const float* yk = ys + kl * 128;

        float acc0 = 0.f, acc1 = 0.f;
        #pragma unroll
        for (int oo = 0; oo < 8; oo++) {
            const float ym1 = yk[oo * 16 + u0];       // w-1 (pad at col 0)
            const float yc0 = yk[oo * 16 + u0 + 1];   // w
            const float yc1 = yk[oo * 16 + u0 + 2];   // w+1
            const float yp2 = yk[oo * 16 + u0 + 3];   // w+2 (pad at col 15)
            const float wa = ws2[(i2 * 8 + oo) * 3 + 0];
            const float wb = ws2[(i2 * 8 + oo) * 3 + 1];
            const float wc = ws2[(i2 * 8 + oo) * 3 + 2];
            acc0 = fmaf(ym1, wa, acc0);
            acc0 = fmaf(yc0, wb, acc0);
            acc0 = fmaf(yc1, wc, acc0);
            acc1 = fmaf(yc0, wa, acc1);
            acc1 = fmaf(yc1, wb, acc1);
            acc1 = fmaf(yp2, wc, acc1);
        }

        float2* po = (float2*)(out + (i2 * 16 + kp * 2 + kl) * 196 + h * 14 + u0);
        *po = make_float2(acc0, acc1);
    }
}

extern "C" void kernel_launch(void* const* d_in, const int* in_sizes, int n_in,
                              void* d_out, int out_size)
{
    const float* x  = (const float*)d_in[0];   // (1,512,14,14)
    const float* w1 = (const float*)d_in[1];   // (16,64,3)
    const float* w2 = (const float*)d_in[2];   // (32,8,3)
    float* out = (float*)d_out;                // (1,512,14,14)

    fused_kernel<<<dim3(8, 14), 896>>>(x, w1, w2, out);
}

// round 12
// speedup vs baseline: 1.0037x; 1.0037x over previous
#include <cuda_runtime.h>

// Fused shift + grouped conv(H taps, w1) + grouped conv(W taps, w2).
//
// x:  (1,512,14,14) fp32, channel c = i*8 + o   (i=0..63, o=0..7)
// Stage 1: y[k,o,h,w] = sum_{i,j} x[(h+j-2) mod 14][..] * w1[k,i,j],
//          tap j contributes iff 0 <= h+j-1 < 14 (roll +1 along H, zero-pad).
//          Loads always issued (mod-14 row in-bounds); invalid taps
//          neutralized by zeroing the CTA-uniform weight (SEL; this is the
//          known-good regs=51 schedule — do not hoist weights).
// Stage 2: out[(i2*16+k)*196 + h*14 + w] = sum_{o,t} y[k,o,h,w-1+t] * w2[i2,o,t]
//          ys is stored zero-padded along W so stage 2 has no edge predicates;
//          pad columns are written by the edge reducer threads themselves.
//
// Grid (8 k-pairs, 14 h) = 112 CTAs, 896 threads (28 warps).
// Stage-1 thread = (g 0..15 splits i 16-ways, o 0..7, wp 0..6 -> w-pair),
// 4 accumulators (2 k x 2 w) off 12 front-batched volatile loads.
// Stage-2 thread = (i2 0..31, kl 0..1, wp 0..6) on threads < 448.

__device__ __forceinline__ float2 ldg64v(const float2* p) {
    float2 v;
    asm volatile("ld.global.nc.v2.f32 {%0,%1},[%2];"
                 : "=f"(v.x), "=f"(v.y) : "l"(p));
    return v;
}

__global__ void __launch_bounds__(896, 1) fused_kernel(
    const float* __restrict__ x,
    const float* __restrict__ w1,
    const float* __restrict__ w2,
    float* __restrict__ out)
{
    __shared__ float ws1[384];                  // [kl][i][j], this CTA's k-pair
    __shared__ float ws2[768];                  // all of w2
    __shared__ float part[16 * 2 * 8 * 16];     // [g][kl][o][w pad 16]
    __shared__ float ys[2 * 8 * 16];            // [kl][o][1+w..14, 0/15 = zero]

    const int kp  = blockIdx.x;   // 0..7   (k = kp*2 + kl)
    const int h   = blockIdx.y;   // 0..13
    const int tid = threadIdx.x;  // 0..895

    // ---- stage-1 thread decode ----
    const int g   = tid / 56;          // 0..15 (i-split)
    const int rem = tid - g * 56;
    const int o   = rem / 7;           // 0..7
    const int wp  = rem - o * 7;       // 0..6  -> w0 = 2*wp
    const int w0  = wp * 2;

    // taps: source rows (mod-14 roll); always in-bounds
    const int  r0 = (h + 12) % 14;     // j=0, contributes iff h >= 1
    const int  r1 = (h + 13) % 14;     // j=1, always
    const int  r2 = h;                 // j=2, contributes iff h <= 12
    const bool v0 = (h >= 1);
    const bool v2 = (h <= 12);

    const float2* __restrict__ px = (const float2*)x;
    // float2 index of x[(i*8+o)*196 + r*14 + w0] = (i*8+o)*98 + r*7 + wp
    const int e0 = o * 98 + r0 * 7 + wp;
    const int e1 = o * 98 + r1 * 7 + wp;
    const int e2 = o * 98 + r2 * 7 + wp;
    const int ib = g * 4;

    // ---- front-batch all 12 x loads (volatile: cannot sink past barrier) ----
    float2 xv0[4], xv1[4], xv2[4];
    #pragma unroll
    for (int ii = 0; ii < 4; ii++) {
        const int off = (ib + ii) * 784;   // i*8*98
        xv0[ii] = ldg64v(px + off + e0);
        xv1[ii] = ldg64v(px + off + e1);
        xv2[ii] = ldg64v(px + off + e2);
    }

    // ---- weight staging (latency overlaps the x loads above) ----
    if (tid < 384) ws1[tid] = __ldg(w1 + kp * 384 + tid);
    if (tid < 768) ws2[tid] = __ldg(w2 + tid);

    __syncthreads();   // ws1/ws2 visible; x loads in flight behind it

    // ---- stage 1 FMAs: 2 k x 2 w accumulators off the same x registers ----
    float a0A = 0.f, a0B = 0.f;        // kl=0: w0, w0+1
    float a1A = 0.f, a1B = 0.f;        // kl=1: w0, w0+1
    #pragma unroll
    for (int ii = 0; ii < 4; ii++) {
        const int i = ib + ii;
        const float wa0 = v0 ? ws1[i * 3 + 0] : 0.f;
        const float wb0 =      ws1[i * 3 + 1];
        const float wc0 = v2 ? ws1[i * 3 + 2] : 0.f;
        const float wa1 = v0 ? ws1[192 + i * 3 + 0] : 0.f;
        const float wb1 =      ws1[192 + i * 3 + 1];
        const float wc1 = v2 ? ws1[192 + i * 3 + 2] : 0.f;
        a0A = fmaf(xv0[ii].x, wa0, a0A);
        a0A = fmaf(xv1[ii].x, wb0, a0A);
        a0A = fmaf(xv2[ii].x, wc0, a0A);
        a0B = fmaf(xv0[ii].y, wa0, a0B);
        a0B = fmaf(xv1[ii].y, wb0, a0B);
        a0B = fmaf(xv2[ii].y, wc0, a0B);
        a1A = fmaf(xv0[ii].x, wa1, a1A);
        a1A = fmaf(xv1[ii].x, wb1, a1A);
        a1A = fmaf(xv2[ii].x, wc1, a1A);
        a1B = fmaf(xv0[ii].y, wa1, a1B);
        a1B = fmaf(xv1[ii].y, wb1, a1B);
        a1B = fmaf(xv2[ii].y, wc1, a1B);
    }
    {
        float2* pp = (float2*)part;
        // part[g][kl][o][w16]: float2 index = (g*256 + kl*128 + o*16 + w0)/2
        pp[(g * 256 + o * 16 + w0) >> 1]       = make_float2(a0A, a0B);
        pp[(g * 256 + 128 + o * 16 + w0) >> 1] = make_float2(a1A, a1B);
    }
    __syncthreads();

    // ---- reduce the 16 i-partials per (kl,o,w): 224 threads; edge threads
    //      also write the zero-pad columns (cols 0 and 15 of each row) ----
    if (tid < 224) {
        const int kl  = tid / 112;
        const int r2d = tid - kl * 112;
        const int oo  = r2d / 14;
        const int ww  = r2d - oo * 14;
        const int b   = kl * 128 + oo * 16 + ww;
        float s0 = 0.f, s1 = 0.f, s2 = 0.f, s3 = 0.f;
        #pragma unroll
        for (int gg = 0; gg < 4; gg++) {
            s0 += part[(gg)      * 256 + b];
            s1 += part[(gg + 4)  * 256 + b];
            s2 += part[(gg + 8)  * 256 + b];
            s3 += part[(gg + 12) * 256 + b];
        }
        const int row = kl * 128 + oo * 16;
        // ys stores w at column ww+1; columns 0 and 15 are zero pads
        ys[row + ww + 1] = (s0 + s1) + (s2 + s3);
        if (ww == 0)  ys[row]      = 0.f;
        if (ww == 13) ys[row + 15] = 0.f;
    }
    __syncthreads();

    // ---- stage 2: thread = (i2, kl, wp); no edge predicates (ys padded) ----
    if (tid < 448) {
        const int i2  = tid / 14;          // 0..31
        const int r2d = tid - i2 * 14;
        const int kl  = r2d / 7;           // 0..1
        const int wp2 = r2d - kl * 7;      // 0..6
        const int u0  = wp2 * 2;           // w = u0, u0+1
        const float* yk = ys + kl * 128;

        float acc0 = 0.f, acc1 = 0.f;
        #pragma unroll
        for (int oo = 0; oo < 8; oo++) {
            const float ym1 = yk[oo * 16 + u0];       // w-1 (pad at col 0)
            const float yc0 = yk[oo * 16 + u0 + 1];   // w
            const float yc1 = yk[oo * 16 + u0 + 2];   // w+1
            const float yp2 = yk[oo * 16 + u0 + 3];   // w+2 (pad at col 15)
            const float wa = ws2[(i2 * 8 + oo) * 3 + 0];
            const float wb = ws2[(i2 * 8 + oo) * 3 + 1];
            const float wc = ws2[(i2 * 8 + oo) * 3 + 2];
            acc0 = fmaf(ym1, wa, acc0);
            acc0 = fmaf(yc0, wb, acc0);
            acc0 = fmaf(yc1, wc, acc0);
            acc1 = fmaf(yc0, wa, acc1);
            acc1 = fmaf(yc1, wb, acc1);
            acc1 = fmaf(yp2, wc, acc1);
        }

        float2* po = (float2*)(out + (i2 * 16 + kp * 2 + kl) * 196 + h * 14 + u0);
        *po = make_float2(acc0, acc1);
    }
}

extern "C" void kernel_launch(void* const* d_in, const int* in_sizes, int n_in,
                              void* d_out, int out_size)
{
    const float* x  = (const float*)d_in[0];   // (1,512,14,14)
    const float* w1 = (const float*)d_in[1];   // (16,64,3)
    const float* w2 = (const float*)d_in[2];   // (32,8,3)
    float* out = (float*)d_out;                // (1,512,14,14)

    fused_kernel<<<dim3(8, 14), 896>>>(x, w1, w2, out);
}